// round 7
// baseline (speedup 1.0000x reference)
#include <cuda_runtime.h>

#define BDIM 32
#define TDIM 512
#define IDIM 512
#define HDIM 1024
#define G4   4096
#define NBLK 128
#define CPB  8
#define HPAD 36                 // hsm row stride (floats): banks (4l+e), conflict-free

typedef unsigned long long ull;

__device__ float g_xg[(size_t)BDIM * TDIM * G4];   // [B,T,4H]
__device__ float g_hkb[2][HDIM * BDIM];            // h as [k][b], double-buffered
__device__ int   g_count;

__device__ __forceinline__ ull ffma2(ull a, ull b, ull c) {
    ull d; asm("fma.rn.f32x2 %0, %1, %2, %3;" : "=l"(d) : "l"(a), "l"(b), "l"(c));
    return d;
}
__device__ __forceinline__ ull add2(ull a, ull b) {
    ull d; asm("add.rn.f32x2 %0, %1, %2;" : "=l"(d) : "l"(a), "l"(b));
    return d;
}
__device__ __forceinline__ ull pack2(float x, float y) {
    ull d; asm("mov.b64 %0, {%1, %2};" : "=l"(d) : "f"(x), "f"(y));
    return d;
}
__device__ __forceinline__ float2 unpack2(ull v) {
    float2 r; asm("mov.b64 {%0, %1}, %2;" : "=f"(r.x), "=f"(r.y) : "l"(v));
    return r;
}
__device__ __forceinline__ int ld_acquire(const int* p) {
    int v; asm volatile("ld.global.acquire.gpu.b32 %0, [%1];" : "=r"(v) : "l"(p));
    return v;
}

__global__ void init_state_kernel() {
    int i = blockIdx.x * blockDim.x + threadIdx.x;
    if (i < HDIM * BDIM) g_hkb[0][i] = 0.0f;
    if (i == 0) g_count = 0;
}

// ---------------------------------------------------------------------------
// Phase 1 GEMM (f32x2): xg[16384,4096] = X*Wx^T + (bx+bh)
// ---------------------------------------------------------------------------
__global__ void __launch_bounds__(256, 2) gemm_xg_kernel(
    const float* __restrict__ X, const float* __restrict__ Wx,
    const float* __restrict__ bx, const float* __restrict__ bh)
{
    __shared__ float As[16][128];
    __shared__ float Bs[16][128];

    const int tid = threadIdx.x;
    const int bm  = blockIdx.y * 128;
    const int bn  = blockIdx.x * 128;
    const int lr = tid >> 2;
    const int lc = (tid & 3) << 2;
    const int tm = (tid >> 4) << 3;
    const int tn = (tid & 15) << 3;

    ull acc2[4][8];
#pragma unroll
    for (int ip = 0; ip < 4; ip++)
#pragma unroll
        for (int j = 0; j < 8; j++) acc2[ip][j] = 0ULL;

    for (int k0 = 0; k0 < IDIM; k0 += 16) {
#pragma unroll
        for (int r = 0; r < 2; r++) {
            const int row = lr + r * 64;
            float4 va = *(const float4*)(X  + (size_t)(bm + row) * IDIM + k0 + lc);
            As[lc + 0][row] = va.x; As[lc + 1][row] = va.y;
            As[lc + 2][row] = va.z; As[lc + 3][row] = va.w;
            float4 vb = *(const float4*)(Wx + (size_t)(bn + row) * IDIM + k0 + lc);
            Bs[lc + 0][row] = vb.x; Bs[lc + 1][row] = vb.y;
            Bs[lc + 2][row] = vb.z; Bs[lc + 3][row] = vb.w;
        }
        __syncthreads();

#pragma unroll
        for (int kk = 0; kk < 16; kk++) {
            const ull* ap = (const ull*)(&As[kk][tm]);
            ull a2[4] = {ap[0], ap[1], ap[2], ap[3]};
            float4 b0 = *(const float4*)(&Bs[kk][tn]);
            float4 b1 = *(const float4*)(&Bs[kk][tn + 4]);
            ull bd[8];
            bd[0] = pack2(b0.x, b0.x); bd[1] = pack2(b0.y, b0.y);
            bd[2] = pack2(b0.z, b0.z); bd[3] = pack2(b0.w, b0.w);
            bd[4] = pack2(b1.x, b1.x); bd[5] = pack2(b1.y, b1.y);
            bd[6] = pack2(b1.z, b1.z); bd[7] = pack2(b1.w, b1.w);
#pragma unroll
            for (int ip = 0; ip < 4; ip++)
#pragma unroll
                for (int j = 0; j < 8; j++)
                    acc2[ip][j] = ffma2(a2[ip], bd[j], acc2[ip][j]);
        }
        __syncthreads();
    }

    float bias[8];
#pragma unroll
    for (int j = 0; j < 8; j++) bias[j] = bx[bn + tn + j] + bh[bn + tn + j];

#pragma unroll
    for (int ip = 0; ip < 4; ip++) {
        float lo[8], hi[8];
#pragma unroll
        for (int j = 0; j < 8; j++) {
            float2 v = unpack2(acc2[ip][j]);
            lo[j] = v.x + bias[j];
            hi[j] = v.y + bias[j];
        }
        float* o0 = g_xg + (size_t)(bm + tm + 2 * ip)     * G4 + bn + tn;
        float* o1 = g_xg + (size_t)(bm + tm + 2 * ip + 1) * G4 + bn + tn;
        *(float4*)(o0)     = make_float4(lo[0], lo[1], lo[2], lo[3]);
        *(float4*)(o0 + 4) = make_float4(lo[4], lo[5], lo[6], lo[7]);
        *(float4*)(o1)     = make_float4(hi[0], hi[1], hi[2], hi[3]);
        *(float4*)(o1 + 4) = make_float4(hi[4], hi[5], hi[6], hi[7]);
    }
}

// ---------------------------------------------------------------------------
// Phase 2: persistent recurrence. warp = cell, lane = k-slice; Wh in registers
// as f32x2 cross-gate pairs; h staged via cp.async into smem [k][b] each step.
// Batch processed in 4 passes of 8; xor reduce-scatter -> lane = (b, gate).
// ---------------------------------------------------------------------------
__global__ void __launch_bounds__(256, 1) lstm_persistent_kernel(
    const float* __restrict__ Wh,
    float* __restrict__ out)
{
    extern __shared__ float hsm[];              // [HDIM][HPAD]

    const int tid = threadIdx.x;
    const int l   = tid & 31;                   // lane = k-slice
    const int w   = tid >> 5;                   // warp = local cell
    const int n   = blockIdx.x * CPB + w;       // global cell

    // ---- one-time: Wh rows for cell n into registers (f32x2 gate pairs) ----
    ull wif[32], wgo[32];
#pragma unroll
    for (int j = 0; j < 32; j++) {
        const int k = (j << 5) + l;
        wif[j] = pack2(Wh[(size_t)n * HDIM + k],
                       Wh[(size_t)(n + HDIM) * HDIM + k]);
        wgo[j] = pack2(Wh[(size_t)(n + 2 * HDIM) * HDIM + k],
                       Wh[(size_t)(n + 3 * HDIM) * HDIM + k]);
    }

    // lane decomposition for reduce-scatter result
    const int  bit4 = (l >> 4) & 1, bit3 = (l >> 3) & 1, bit2 = (l >> 2) & 1;
    const int  bit1 = (l >> 1) & 1, bit0 = l & 1;
    const int  gate = l & 3;                    // 0=i 1=f 2=g 3=o
    const int  bsub = l >> 2;                   // batch index within pass (0..7)
    const bool isG  = (gate == 2);
    const int  gbase = l & ~3;

    // staging addresses (cp.async, 16B each)
    const unsigned hrow0 = (unsigned)(tid >> 3);       // k base
    const unsigned hcol  = (unsigned)((tid & 7) << 2); // b base
    const unsigned sbase = (unsigned)__cvta_generic_to_shared(hsm);

    float cst[4] = {0.0f, 0.0f, 0.0f, 0.0f};

    for (int t = 0; t < TDIM; t++) {
        // ---- stage h(t): g_hkb[t&1] ([k][b], coalesced) -> hsm[k][b] ----
        {
            const float* src = g_hkb[t & 1] + (tid << 2);
#pragma unroll
            for (int r = 0; r < 32; r++) {
                const unsigned d = sbase + ((hrow0 + (r << 5)) * HPAD + hcol) * 4u;
                asm volatile("cp.async.cg.shared.global [%0], [%1], 16;"
                             :: "r"(d), "l"(src + (r << 10)) : "memory");
            }
            asm volatile("cp.async.commit_group;" ::: "memory");
        }

        // prefetch xg for all 4 passes (lane = (b, gate))
        float xgv[4];
#pragma unroll
        for (int p = 0; p < 4; p++)
            xgv[p] = __ldg(g_xg + ((size_t)(p * 8 + bsub) * TDIM + t) * G4
                           + (size_t)gate * HDIM + n);

        asm volatile("cp.async.wait_group 0;" ::: "memory");
        __syncthreads();

#pragma unroll
        for (int p = 0; p < 4; p++) {
            ull aif[8], ago[8];
#pragma unroll
            for (int b = 0; b < 8; b++) { aif[b] = 0ULL; ago[b] = 0ULL; }

            const float* hp = hsm + (size_t)l * HPAD + (p << 3);
#pragma unroll
            for (int j = 0; j < 32; j++) {
                const float4 h0 = *(const float4*)(hp + (size_t)(j << 5) * HPAD);
                const float4 h1 = *(const float4*)(hp + (size_t)(j << 5) * HPAD + 4);
                const ull hd0 = pack2(h0.x, h0.x), hd1 = pack2(h0.y, h0.y);
                const ull hd2 = pack2(h0.z, h0.z), hd3 = pack2(h0.w, h0.w);
                const ull hd4 = pack2(h1.x, h1.x), hd5 = pack2(h1.y, h1.y);
                const ull hd6 = pack2(h1.z, h1.z), hd7 = pack2(h1.w, h1.w);
                aif[0] = ffma2(hd0, wif[j], aif[0]); ago[0] = ffma2(hd0, wgo[j], ago[0]);
                aif[1] = ffma2(hd1, wif[j], aif[1]); ago[1] = ffma2(hd1, wgo[j], ago[1]);
                aif[2] = ffma2(hd2, wif[j], aif[2]); ago[2] = ffma2(hd2, wgo[j], ago[2]);
                aif[3] = ffma2(hd3, wif[j], aif[3]); ago[3] = ffma2(hd3, wgo[j], ago[3]);
                aif[4] = ffma2(hd4, wif[j], aif[4]); ago[4] = ffma2(hd4, wgo[j], ago[4]);
                aif[5] = ffma2(hd5, wif[j], aif[5]); ago[5] = ffma2(hd5, wgo[j], ago[5]);
                aif[6] = ffma2(hd6, wif[j], aif[6]); ago[6] = ffma2(hd6, wgo[j], ago[6]);
                aif[7] = ffma2(hd7, wif[j], aif[7]); ago[7] = ffma2(hd7, wgo[j], ago[7]);
            }

            // ---- reduce-scatter: sum over 32 lanes, scatter (b, gate) ----
            ull VA[4], VG[4];
#pragma unroll
            for (int v = 0; v < 4; v++) {
                VA[v] = add2(bit4 ? aif[4 + v] : aif[v],
                             __shfl_xor_sync(0xffffffffu, bit4 ? aif[v] : aif[4 + v], 16));
                VG[v] = add2(bit4 ? ago[4 + v] : ago[v],
                             __shfl_xor_sync(0xffffffffu, bit4 ? ago[v] : ago[4 + v], 16));
            }
            ull WA[2], WG[2];
#pragma unroll
            for (int v = 0; v < 2; v++) {
                WA[v] = add2(bit3 ? VA[2 + v] : VA[v],
                             __shfl_xor_sync(0xffffffffu, bit3 ? VA[v] : VA[2 + v], 8));
                WG[v] = add2(bit3 ? VG[2 + v] : VG[v],
                             __shfl_xor_sync(0xffffffffu, bit3 ? VG[v] : VG[2 + v], 8));
            }
            const ull XA = add2(bit2 ? WA[1] : WA[0],
                                __shfl_xor_sync(0xffffffffu, bit2 ? WA[0] : WA[1], 4));
            const ull XG = add2(bit2 ? WG[1] : WG[0],
                                __shfl_xor_sync(0xffffffffu, bit2 ? WG[0] : WG[1], 4));
            const ull Y = add2(bit1 ? XG : XA,
                               __shfl_xor_sync(0xffffffffu, bit1 ? XA : XG, 2));
            const float2 y2 = unpack2(Y);
            float F = (bit0 ? y2.y : y2.x)
                    + __shfl_xor_sync(0xffffffffu, bit0 ? y2.x : y2.y, 1);

            // ---- gate nonlinearity: sigmoid via tanh identity ----
            F += xgv[p];
            float a = tanhf(isG ? F : 0.5f * F);
            a = isG ? a : 0.5f * (1.0f + a);

            const float vi = __shfl_sync(0xffffffffu, a, gbase);
            const float vf = __shfl_sync(0xffffffffu, a, gbase + 1);
            const float vg = __shfl_sync(0xffffffffu, a, gbase + 2);
            const float vo = __shfl_sync(0xffffffffu, a, gbase + 3);

            cst[p] = vf * cst[p] + vi * vg;
            const float h = vo * tanhf(cst[p]);

            if (gate == 0) {
                const int b = p * 8 + bsub;
                g_hkb[(t + 1) & 1][(n << 5) + b] = h;                     // [k][b]
                out[((size_t)b * TDIM + t) * HDIM + n] = h;               // [B,T,H]
            }
        }

        // ---- grid barrier ----
        if (t < TDIM - 1) {
            __threadfence();
            __syncthreads();
            if (tid == 0) {
                atomicAdd(&g_count, 1);
                while (ld_acquire(&g_count) < NBLK * (t + 1)) { }
            }
            __syncthreads();
        }
    }
}

// ---------------------------------------------------------------------------
extern "C" void kernel_launch(void* const* d_in, const int* in_sizes, int n_in,
                              void* d_out, int out_size)
{
    const float* x  = (const float*)d_in[0];
    const float* Wx = (const float*)d_in[1];
    const float* bx = (const float*)d_in[2];
    const float* Wh = (const float*)d_in[3];
    const float* bh = (const float*)d_in[4];
    float* out = (float*)d_out;
    (void)in_sizes; (void)n_in; (void)out_size;

    const int SMEM_BYTES = HDIM * HPAD * (int)sizeof(float);   // 147456
    cudaFuncSetAttribute(lstm_persistent_kernel,
                         cudaFuncAttributeMaxDynamicSharedMemorySize, SMEM_BYTES);

    init_state_kernel<<<(HDIM * BDIM + 255) / 256, 256>>>();

    dim3 ggrid(G4 / 128, (BDIM * TDIM) / 128);
    gemm_xg_kernel<<<ggrid, 256>>>(x, Wx, bx, bh);

    lstm_persistent_kernel<<<NBLK, 256, SMEM_BYTES>>>(Wh, out);
}